// round 8
// baseline (speedup 1.0000x reference)
#include <cuda_runtime.h>
#include <cuda_bf16.h>
#include <cstdint>

// out[b] = ||x_b||^2 * (x_b^T S x_b),  S=(rho+rho^T)/2, x=h+l, S=Sh+Sl:
//   q ~= h^T Sh (h + 2l) + h^T Sl h        (2 GEMM terms; dropped O(eps^2))
// R8: whole B slab (128 rows x K=256, hi+lo) resident in smem; ONE cp.async
// wait + ONE syncthreads, then a barrier-free 16-step register-pipelined loop.

#define BATCH 4096
#define DIMX 256
#define TILE_M 64
#define TILE_N 128
#define NTHREADS 512

__device__ __nv_bfloat16 g_Sh[DIMX * DIMX];
__device__ __nv_bfloat16 g_Sl[DIMX * DIMX];
__device__ float g_q[BATCH];
__device__ int   g_cnt[BATCH / TILE_M];

// ---- dynamic smem layout (bytes) ----
#define A_STRIDE 264        // bf16/row (528B pitch -> conflict-free ldsm)
#define B_STRIDE 264        // full K row + pad
#define SM_AH    0                          // 64 x 528  = 33792
#define SM_AL    33792
#define SM_BH    67584                      // 128 x 528 = 67584
#define SM_BL    135168
#define SM_QP    202752                     // float[16][16] = 1024
#define SM_SN    203776                     // float[128] row-norm halves
#define SM_FLAG  204288
#define SMEM_TOTAL 204416

__device__ __forceinline__ uint32_t smem_u32(const void* p) {
    uint32_t a;
    asm("{ .reg .u64 t; cvta.to.shared.u64 t, %1; cvt.u32.u64 %0, t; }"
        : "=r"(a) : "l"(p));
    return a;
}
__device__ __forceinline__ void cp16(uint32_t dst, const void* src) {
    asm volatile("cp.async.cg.shared.global [%0], [%1], 16;" :: "r"(dst), "l"(src));
}
__device__ __forceinline__ void mma16816(float* c, const uint32_t* a, const uint32_t* b) {
    asm volatile(
        "mma.sync.aligned.m16n8k16.row.col.f32.bf16.bf16.f32 "
        "{%0,%1,%2,%3}, {%4,%5,%6,%7}, {%8,%9}, {%0,%1,%2,%3};"
        : "+f"(c[0]), "+f"(c[1]), "+f"(c[2]), "+f"(c[3])
        : "r"(a[0]), "r"(a[1]), "r"(a[2]), "r"(a[3]), "r"(b[0]), "r"(b[1]));
}
__device__ __forceinline__ void ldsm_x4(uint32_t* r, uint32_t addr) {
    asm volatile("ldmatrix.sync.aligned.m8n8.x4.shared.b16 {%0,%1,%2,%3}, [%4];"
                 : "=r"(r[0]), "=r"(r[1]), "=r"(r[2]), "=r"(r[3]) : "r"(addr));
}
__device__ __forceinline__ void split4(const float4 v, uint2& hi, uint2& lo) {
    __nv_bfloat162 h01 = __float22bfloat162_rn(make_float2(v.x, v.y));
    __nv_bfloat162 h23 = __float22bfloat162_rn(make_float2(v.z, v.w));
    float2 f01 = __bfloat1622float2(h01);
    float2 f23 = __bfloat1622float2(h23);
    __nv_bfloat162 l01 = __float22bfloat162_rn(make_float2(v.x - f01.x, v.y - f01.y));
    __nv_bfloat162 l23 = __float22bfloat162_rn(make_float2(v.z - f23.x, v.w - f23.y));
    hi.x = *reinterpret_cast<const uint32_t*>(&h01);
    hi.y = *reinterpret_cast<const uint32_t*>(&h23);
    lo.x = *reinterpret_cast<const uint32_t*>(&l01);
    lo.y = *reinterpret_cast<const uint32_t*>(&l23);
}

// ---- cvt: S = (rho + rho^T)/2 via smem tile transpose, split bf16 hi/lo ----
__global__ void cvt_sym(const float* __restrict__ R) {
    __shared__ float tB[32][33];
    const int ti = blockIdx.x >> 3, tj = blockIdx.x & 7;
    const int tx = threadIdx.x & 31, ty = threadIdx.x >> 5;   // 32 x 8
    // load transpose-source tile (tj,ti) coalesced
    #pragma unroll
    for (int i = 0; i < 4; i++)
        tB[ty + i * 8][tx] = R[(size_t)(tj * 32 + ty + i * 8) * DIMX + ti * 32 + tx];
    __syncthreads();
    #pragma unroll
    for (int i = 0; i < 4; i++) {
        const int r = ti * 32 + ty + i * 8, c = tj * 32 + tx;
        const float s = 0.5f * (R[(size_t)r * DIMX + c] + tB[tx][ty + i * 8]);
        const __nv_bfloat16 h = __float2bfloat16(s);
        const __nv_bfloat16 l = __float2bfloat16(s - __bfloat162float(h));
        g_Sh[(size_t)r * DIMX + c] = h;
        g_Sl[(size_t)r * DIMX + c] = l;
    }
}

__global__ __launch_bounds__(NTHREADS, 1)
void qmd_mma(const float* __restrict__ X, float* __restrict__ out) {
    extern __shared__ char smem[];
    const uint32_t sb = smem_u32(smem);
    const int t = threadIdx.x;
    const int wid = t >> 5;
    const int lane = t & 31;

    const int mt = blockIdx.x >> 1;          // M tile 0..63
    const int nh = blockIdx.x & 1;           // N half
    const int b0 = mt * TILE_M;
    const int ncol0 = nh * TILE_N;

    const int mg = wid >> 2;                 // 0..3 : 16-row group
    const int ng = wid & 3;                  // 0..3 : 32-col group (slab-local)
    const int n_base = ng * 32;

    // ---- issue ALL B cp.async (hi+lo, 128 rows x 32 16B-units each) ----
    #pragma unroll
    for (int i = 0; i < 16; i++) {
        const int f = t + i * NTHREADS;              // 0..8191
        const int arr = f >> 12, rem = f & 4095;
        const int n = rem >> 5, c = rem & 31;        // 128 rows x 32 units
        const uint32_t dst = sb + (arr ? SM_BL : SM_BH) + n * (B_STRIDE * 2) + c * 16;
        const __nv_bfloat16* src = (arr ? g_Sl : g_Sh) + (size_t)(ncol0 + n) * DIMX + c * 8;
        cp16(dst, src);
    }
    asm volatile("cp.async.commit_group;" ::: "memory");

    // ---- load + convert A tile; fold ||x||^2 from f32 (overlaps cp.async) ----
    {
        const float4* __restrict__ Xg = reinterpret_cast<const float4*>(X);
        float* sn = reinterpret_cast<float*>(smem + SM_SN);
        #pragma unroll
        for (int i = 0; i < 8; i++) {
            const int f = t + i * NTHREADS;          // 0..4095
            const int r = f >> 6, c4 = f & 63;       // all lanes of a warp: same r
            float4 v = Xg[(size_t)(b0 + r) * (DIMX / 4) + c4];
            uint2 hi, lo;
            split4(v, hi, lo);
            const uint32_t off = r * (A_STRIDE * 2) + c4 * 8;
            *reinterpret_cast<uint2*>(smem + SM_AH + off) = hi;
            *reinterpret_cast<uint2*>(smem + SM_AL + off) = lo;
            float d = v.x * v.x + v.y * v.y + v.z * v.z + v.w * v.w;
            #pragma unroll
            for (int o = 16; o > 0; o >>= 1)
                d += __shfl_xor_sync(0xffffffffu, d, o);
            if (lane == 0) sn[r * 2 + (wid & 1)] = d;    // half-row sum
        }
    }

    // ldmatrix base addresses
    const int m_idx = lane >> 3;
    const uint32_t a_row = mg * 16 + (m_idx & 1) * 8 + (lane & 7);
    const uint32_t a_base = a_row * (A_STRIDE * 2) + (m_idx >> 1) * 16;
    const uint32_t b_rowpart = (m_idx >> 1) * 8 + (lane & 7);
    const uint32_t b_base0 = (n_base + b_rowpart) * (B_STRIDE * 2) + (m_idx & 1) * 16;
    const uint32_t b_base1 = (n_base + 16 + b_rowpart) * (B_STRIDE * 2) + (m_idx & 1) * 16;

    float acc_a[4][4], acc_b[4][4];
    #pragma unroll
    for (int ni = 0; ni < 4; ni++)
        #pragma unroll
        for (int e = 0; e < 4; e++) { acc_a[ni][e] = 0.0f; acc_b[ni][e] = 0.0f; }

    asm volatile("cp.async.wait_group 0;" ::: "memory");
    __syncthreads();                          // the ONE barrier before compute

    const uint32_t ah = sb + SM_AH + a_base;
    const uint32_t bh = sb + SM_BH;
    const uint32_t bl = sb + SM_BL;

    uint32_t aH[2][4], bHf[2][8], bLf[2][8];
    ldsm_x4(aH[0], ah);
    ldsm_x4(&bHf[0][0], bh + b_base0);
    ldsm_x4(&bHf[0][4], bh + b_base1);
    ldsm_x4(&bLf[0][0], bl + b_base0);
    ldsm_x4(&bLf[0][4], bl + b_base1);

    #pragma unroll
    for (int k16 = 0; k16 < 16; k16++) {      // K = 256, barrier-free
        const int cur = k16 & 1, nxt = cur ^ 1;
        if (k16 < 15) {
            const uint32_t ko = (k16 + 1) * 32;     // 16 cols * 2B
            ldsm_x4(aH[nxt], ah + ko);
            ldsm_x4(&bHf[nxt][0], bh + b_base0 + ko);
            ldsm_x4(&bHf[nxt][4], bh + b_base1 + ko);
            ldsm_x4(&bLf[nxt][0], bl + b_base0 + ko);
            ldsm_x4(&bLf[nxt][4], bl + b_base1 + ko);
        }
        #pragma unroll
        for (int ni = 0; ni < 4; ni++) {
            mma16816(acc_a[ni], aH[cur], &bHf[cur][ni * 2]);   // h^T Sh
            mma16816(acc_b[ni], aH[cur], &bLf[cur][ni * 2]);   // h^T Sl
        }
    }

    // ---- epilogue: q_part = sum_j Za*(h+2l) + Zb*h over this CTA's N slab ----
    const __nv_bfloat16* sAh = reinterpret_cast<const __nv_bfloat16*>(smem + SM_AH);
    const __nv_bfloat16* sAl = reinterpret_cast<const __nv_bfloat16*>(smem + SM_AL);
    float q[2] = {0, 0};
    #pragma unroll
    for (int ni = 0; ni < 4; ni++) {
        const int j0 = ncol0 + n_base + ni * 8 + (lane & 3) * 2;
        const int r0 = mg * 16 + (lane >> 2);
        #pragma unroll
        for (int e = 0; e < 4; e++) {
            const int r = r0 + (e >> 1) * 8;
            const int j = j0 + (e & 1);
            const float xh = __bfloat162float(sAh[r * A_STRIDE + j]);
            const float xl = __bfloat162float(sAl[r * A_STRIDE + j]);
            const int s = e >> 1;
            q[s] = fmaf(acc_a[ni][e], xh + 2.0f * xl, q[s]);
            q[s] = fmaf(acc_b[ni][e], xh, q[s]);
        }
    }
    #pragma unroll
    for (int off = 1; off <= 2; off <<= 1) {
        q[0] += __shfl_xor_sync(0xffffffffu, q[0], off);
        q[1] += __shfl_xor_sync(0xffffffffu, q[1], off);
    }
    float* qp = reinterpret_cast<float*>(smem + SM_QP);
    if ((lane & 3) == 0) {
        qp[wid * 16 + (lane >> 2)] = q[0];
        qp[wid * 16 + (lane >> 2) + 8] = q[1];
    }
    __syncthreads();

    // ---- cross-CTA combine (2 N-halves) ----
    if (t < TILE_M) {
        const int mgf = t >> 4, rloc = t & 15;
        float qs = 0.0f;
        #pragma unroll
        for (int w = 0; w < 4; w++)
            qs += qp[(mgf * 4 + w) * 16 + rloc];
        atomicAdd(&g_q[b0 + t], qs);
    }
    __threadfence();                          // all threads: order writes
    __syncthreads();

    int* flag = reinterpret_cast<int*>(smem + SM_FLAG);
    if (t == 0) {
        const int old = atomicAdd(&g_cnt[mt], 1);
        *flag = (old == 1);
    }
    __syncthreads();

    if (*flag) {                              // second CTA finalizes
        __threadfence();
        if (t < TILE_M) {
            const float* sn = reinterpret_cast<const float*>(smem + SM_SN);
            const float qq = *reinterpret_cast<volatile float*>(&g_q[b0 + t]);
            const float nn = sn[t * 2] + sn[t * 2 + 1];   // local f32 norm
            out[b0 + t] = qq * nn;
            g_q[b0 + t] = 0.0f;               // reset for next replay
        }
        if (t == 0) g_cnt[mt] = 0;
    }
}

extern "C" void kernel_launch(void* const* d_in, const int* in_sizes, int n_in,
                              void* d_out, int out_size) {
    const float* X   = (const float*)d_in[0];
    const float* rho = (const float*)d_in[1];
    float* out = (float*)d_out;

    cvt_sym<<<64, 256>>>(rho);

    cudaFuncSetAttribute(qmd_mma, cudaFuncAttributeMaxDynamicSharedMemorySize, SMEM_TOTAL);
    qmd_mma<<<(out_size / TILE_M) * 2, NTHREADS, SMEM_TOTAL>>>(X, out);
}

// round 9
// speedup vs baseline: 1.6299x; 1.6299x over previous
#include <cuda_runtime.h>
#include <cuda_bf16.h>
#include <cstdint>

// out[b] = ||x_b||^2 * (x_b^T S x_b),  S=(rho+rho^T)/2 (symmetric)
// x = h + l (bf16 split), S = Sh + Sl (bf16 split, both symmetric):
//   q ~= h^T Sh (h + 2l) + h^T Sl h      (dropped terms O(eps^2) ~ 1e-5 rel)
// R9 = R5 pipeline structure (TILE_M=32, full N=256, chunked double-buffered
// cp.async) with the 2-term formulation: 8 HMMA + 5 LDSM per warp-k16.

#define BATCH 4096
#define DIMX 256
#define TILE_M 32
#define NTHREADS 512
#define NKCHUNKS 4          // K chunks of 64

__device__ __nv_bfloat16 g_Sh[DIMX * DIMX];
__device__ __nv_bfloat16 g_Sl[DIMX * DIMX];

// ---- dynamic smem layout (bytes) ----
#define A_STRIDE 264        // bf16 elems/row (528B pitch, conflict-free ldsm)
#define B_STRIDE 72         // bf16 elems/row (144B pitch, conflict-free)
#define SM_AH    0                       // 32 x 264 x2B = 16896
#define SM_AL    16896
#define SM_BH0   33792                   // 256 x 72 x2B = 36864
#define SM_BL0   70656
#define SM_BH1   107520
#define SM_BL1   144384
#define SM_QP    181248                  // float[16][32] = 2048
#define SM_NP    183296                  // float[16][32] = 2048
#define SMEM_TOTAL 185344

__device__ __forceinline__ uint32_t smem_u32(const void* p) {
    uint32_t a;
    asm("{ .reg .u64 t; cvta.to.shared.u64 t, %1; cvt.u32.u64 %0, t; }"
        : "=r"(a) : "l"(p));
    return a;
}
__device__ __forceinline__ void cp16(uint32_t dst, const void* src) {
    asm volatile("cp.async.cg.shared.global [%0], [%1], 16;" :: "r"(dst), "l"(src));
}
__device__ __forceinline__ void cp_commit() {
    asm volatile("cp.async.commit_group;" ::: "memory");
}
__device__ __forceinline__ void mma16816(float* c, const uint32_t* a, const uint32_t* b) {
    asm volatile(
        "mma.sync.aligned.m16n8k16.row.col.f32.bf16.bf16.f32 "
        "{%0,%1,%2,%3}, {%4,%5,%6,%7}, {%8,%9}, {%0,%1,%2,%3};"
        : "+f"(c[0]), "+f"(c[1]), "+f"(c[2]), "+f"(c[3])
        : "r"(a[0]), "r"(a[1]), "r"(a[2]), "r"(a[3]), "r"(b[0]), "r"(b[1]));
}
__device__ __forceinline__ void ldsm_x4(uint32_t* r, uint32_t addr) {
    asm volatile("ldmatrix.sync.aligned.m8n8.x4.shared.b16 {%0,%1,%2,%3}, [%4];"
                 : "=r"(r[0]), "=r"(r[1]), "=r"(r[2]), "=r"(r[3]) : "r"(addr));
}
__device__ __forceinline__ void ldsm_x2(uint32_t* r, uint32_t addr) {
    asm volatile("ldmatrix.sync.aligned.m8n8.x2.shared.b16 {%0,%1}, [%2];"
                 : "=r"(r[0]), "=r"(r[1]) : "r"(addr));
}
__device__ __forceinline__ void split4(const float4 v, uint2& hi, uint2& lo) {
    __nv_bfloat162 h01 = __float22bfloat162_rn(make_float2(v.x, v.y));
    __nv_bfloat162 h23 = __float22bfloat162_rn(make_float2(v.z, v.w));
    float2 f01 = __bfloat1622float2(h01);
    float2 f23 = __bfloat1622float2(h23);
    __nv_bfloat162 l01 = __float22bfloat162_rn(make_float2(v.x - f01.x, v.y - f01.y));
    __nv_bfloat162 l23 = __float22bfloat162_rn(make_float2(v.z - f23.x, v.w - f23.y));
    hi.x = *reinterpret_cast<const uint32_t*>(&h01);
    hi.y = *reinterpret_cast<const uint32_t*>(&h23);
    lo.x = *reinterpret_cast<const uint32_t*>(&l01);
    lo.y = *reinterpret_cast<const uint32_t*>(&l23);
}

// ---- cvt: S = (rho + rho^T)/2 via smem tile transpose, split bf16 hi/lo ----
__global__ void cvt_sym(const float* __restrict__ R) {
    __shared__ float tB[32][33];
    const int ti = blockIdx.x >> 3, tj = blockIdx.x & 7;
    const int tx = threadIdx.x & 31, ty = threadIdx.x >> 5;   // 32 x 8
    #pragma unroll
    for (int i = 0; i < 4; i++)
        tB[ty + i * 8][tx] = R[(size_t)(tj * 32 + ty + i * 8) * DIMX + ti * 32 + tx];
    __syncthreads();
    #pragma unroll
    for (int i = 0; i < 4; i++) {
        const int r = ti * 32 + ty + i * 8, c = tj * 32 + tx;
        const float s = 0.5f * (R[(size_t)r * DIMX + c] + tB[tx][ty + i * 8]);
        const __nv_bfloat16 h = __float2bfloat16(s);
        const __nv_bfloat16 l = __float2bfloat16(s - __bfloat162float(h));
        g_Sh[(size_t)r * DIMX + c] = h;
        g_Sl[(size_t)r * DIMX + c] = l;
    }
}

__global__ __launch_bounds__(NTHREADS, 1)
void qmd_mma(const float* __restrict__ X, float* __restrict__ out) {
    extern __shared__ char smem[];
    const uint32_t sb = smem_u32(smem);
    const int t = threadIdx.x;
    const int wid = t >> 5;
    const int lane = t & 31;
    const int b0 = blockIdx.x * TILE_M;

    // ---- prefetch B chunks 0,1 via cp.async (double buffer) ----
    #pragma unroll
    for (int kb = 0; kb < 2; kb++) {
        const uint32_t bh = kb ? SM_BH1 : SM_BH0;
        const uint32_t bl = kb ? SM_BL1 : SM_BL0;
        #pragma unroll
        for (int i = 0; i < 8; i++) {
            const int f = t + i * NTHREADS;         // 0..4095
            const int arr = f >> 11, rem = f & 2047;
            const int n = rem >> 3, c = rem & 7;
            const uint32_t dst = sb + (arr ? bl : bh) + n * (B_STRIDE * 2) + c * 16;
            const __nv_bfloat16* src = (arr ? g_Sl : g_Sh) + (size_t)n * DIMX + kb * 64 + c * 8;
            cp16(dst, src);
        }
        cp_commit();
    }

    // ---- load + convert A tile (overlaps cp.async) ----
    {
        const float4* __restrict__ Xg = reinterpret_cast<const float4*>(X);
        #pragma unroll
        for (int i = 0; i < 4; i++) {
            const int f = t + i * NTHREADS;         // 0..2047
            const int r = f >> 6, c4 = f & 63;
            float4 v = Xg[(size_t)(b0 + r) * (DIMX / 4) + c4];
            uint2 hi, lo;
            split4(v, hi, lo);
            const uint32_t off = r * (A_STRIDE * 2) + c4 * 8;
            *reinterpret_cast<uint2*>(smem + SM_AH + off) = hi;
            *reinterpret_cast<uint2*>(smem + SM_AL + off) = lo;
        }
    }

    float acc_a[2][2][4], acc_b[2][2][4];
    #pragma unroll
    for (int mi = 0; mi < 2; mi++)
        #pragma unroll
        for (int ni = 0; ni < 2; ni++)
            #pragma unroll
            for (int e = 0; e < 4; e++) { acc_a[mi][ni][e] = 0.0f; acc_b[mi][ni][e] = 0.0f; }

    const int n_base = wid * 16;

    for (int kb = 0; kb < NKCHUNKS; kb++) {
        if (kb == NKCHUNKS - 1)
            asm volatile("cp.async.wait_group 0;" ::: "memory");
        else
            asm volatile("cp.async.wait_group 1;" ::: "memory");
        __syncthreads();

        const uint32_t bh = (kb & 1) ? SM_BH1 : SM_BH0;
        const uint32_t bl = (kb & 1) ? SM_BL1 : SM_BL0;

        #pragma unroll
        for (int k16 = 0; k16 < 4; k16++) {
            const int kcA = kb * 64 + k16 * 16;     // A global col
            const int kcB = k16 * 16;               // B chunk-local col

            // A hi fragments only (2-term formulation)
            uint32_t aH[2][4];
            {
                const int m_idx = lane >> 3;
                const int arow = (m_idx & 1) * 8 + (lane & 7);
                const int acol = kcA + (m_idx >> 1) * 8;
                #pragma unroll
                for (int mi = 0; mi < 2; mi++) {
                    const uint32_t ao = (mi * 16 + arow) * (A_STRIDE * 2) + acol * 2;
                    ldsm_x4(aH[mi], sb + SM_AH + ao);
                }
            }
            // B fragments (Sh, Sl)
            uint32_t bH[2][2], bL[2][2];
            {
                const int l2 = lane & 15;
                const int m_idx = l2 >> 3;
                const int brow = l2 & 7;
                const int bcol = kcB + m_idx * 8;
                #pragma unroll
                for (int ni = 0; ni < 2; ni++) {
                    const uint32_t bo = (n_base + ni * 8 + brow) * (B_STRIDE * 2) + bcol * 2;
                    ldsm_x2(bH[ni], sb + bh + bo);
                    ldsm_x2(bL[ni], sb + bl + bo);
                }
            }
            // 2-term MMAs (8 per k16)
            #pragma unroll
            for (int mi = 0; mi < 2; mi++)
                #pragma unroll
                for (int ni = 0; ni < 2; ni++) {
                    mma16816(acc_a[mi][ni], aH[mi], bH[ni]);   // h^T Sh
                    mma16816(acc_b[mi][ni], aH[mi], bL[ni]);   // h^T Sl
                }
        }
        __syncthreads();

        // prefetch chunk kb+2 into the buffer just consumed
        if (kb < NKCHUNKS - 2) {
            const int nk = kb + 2;
            const uint32_t dbh = (kb & 1) ? SM_BH1 : SM_BH0;
            const uint32_t dbl = (kb & 1) ? SM_BL1 : SM_BL0;
            #pragma unroll
            for (int i = 0; i < 8; i++) {
                const int f = t + i * NTHREADS;
                const int arr = f >> 11, rem = f & 2047;
                const int n = rem >> 3, c = rem & 7;
                const uint32_t dst = sb + (arr ? dbl : dbh) + n * (B_STRIDE * 2) + c * 16;
                const __nv_bfloat16* src = (arr ? g_Sl : g_Sh) + (size_t)n * DIMX + nk * 64 + c * 8;
                cp16(dst, src);
            }
            cp_commit();
        }
    }

    // ---- fused epilogue: q = sum_j Za*(h+2l) + Zb*h ;  n = sum_j (h+l)^2 ----
    const __nv_bfloat16* sAh = reinterpret_cast<const __nv_bfloat16*>(smem + SM_AH);
    const __nv_bfloat16* sAl = reinterpret_cast<const __nv_bfloat16*>(smem + SM_AL);
    float q[4] = {0, 0, 0, 0};
    float nn[4] = {0, 0, 0, 0};
    #pragma unroll
    for (int mi = 0; mi < 2; mi++) {
        #pragma unroll
        for (int ni = 0; ni < 2; ni++) {
            const int j0 = n_base + ni * 8 + (lane & 3) * 2;
            const int r0 = mi * 16 + (lane >> 2);
            #pragma unroll
            for (int e = 0; e < 4; e++) {
                const int r = r0 + (e >> 1) * 8;
                const int j = j0 + (e & 1);
                const float xh = __bfloat162float(sAh[r * A_STRIDE + j]);
                const float xl = __bfloat162float(sAl[r * A_STRIDE + j]);
                const int slot = mi * 2 + (e >> 1);
                q[slot] = fmaf(acc_a[mi][ni][e], xh + 2.0f * xl, q[slot]);
                q[slot] = fmaf(acc_b[mi][ni][e], xh, q[slot]);
                const float xf = xh + xl;
                nn[slot] = fmaf(xf, xf, nn[slot]);
            }
        }
    }
    #pragma unroll
    for (int off = 1; off <= 2; off <<= 1) {
        #pragma unroll
        for (int s = 0; s < 4; s++) {
            q[s] += __shfl_xor_sync(0xffffffffu, q[s], off);
            nn[s] += __shfl_xor_sync(0xffffffffu, nn[s], off);
        }
    }
    float* qp = reinterpret_cast<float*>(smem + SM_QP);
    float* np = reinterpret_cast<float*>(smem + SM_NP);
    if ((lane & 3) == 0) {
        #pragma unroll
        for (int s = 0; s < 4; s++) {
            const int r = (lane >> 2) + s * 8;
            qp[wid * 32 + r] = q[s];
            np[wid * 32 + r] = nn[s];
        }
    }
    __syncthreads();

    if (t < TILE_M) {
        float qq = 0.0f, ns = 0.0f;
        #pragma unroll
        for (int w = 0; w < 16; w++) {
            qq += qp[w * 32 + t];
            ns += np[w * 32 + t];
        }
        out[b0 + t] = qq * ns;
    }
}

extern "C" void kernel_launch(void* const* d_in, const int* in_sizes, int n_in,
                              void* d_out, int out_size) {
    const float* X   = (const float*)d_in[0];
    const float* rho = (const float*)d_in[1];
    float* out = (float*)d_out;

    cvt_sym<<<64, 256>>>(rho);

    cudaFuncSetAttribute(qmd_mma, cudaFuncAttributeMaxDynamicSharedMemorySize, SMEM_TOTAL);
    qmd_mma<<<out_size / TILE_M, NTHREADS, SMEM_TOTAL>>>(X, out);
}